// round 15
// baseline (speedup 1.0000x reference)
#include <cuda_runtime.h>
#include <cstddef>
#include <cstdint>

#define E_BONDS   200000
#define NATOMS    100000
#define HID       128
#define MAX_NB    15
#define BFD       23
#define AFD       18
#define AIN       146
#define AINP      148
#define NMOLS     2000
#define NPASS     5

#define NPAIR     8              // producer/consumer pairs per CTA
#define SLOT_S    132            // slot row stride (floats); conflict-free
#define SLOT_F    (16 * SLOT_S)  // floats per slot (16-row tile)
#define RING_OFF  (HID * HID)
#define MS_SMEM   ((HID * HID + NPAIR * 2 * SLOT_F) * 4)   // 200704 B

// ---- scratch ----
__device__ float g_binput[(size_t)E_BONDS * HID];
__device__ float g_msgA  [(size_t)E_BONDS * HID];
__device__ float g_msgB  [(size_t)E_BONDS * HID];
__device__ float g_atomh [(size_t)NATOMS  * HID];

// ---- packed f32x2 helpers ----
__device__ __forceinline__ unsigned long long pack2(float lo, float hi) {
    unsigned long long r;
    asm("mov.b64 %0, {%1, %2};" : "=l"(r) : "f"(lo), "f"(hi));
    return r;
}
__device__ __forceinline__ void unpack2(unsigned long long v, float& lo, float& hi) {
    asm("mov.b64 {%0, %1}, %2;" : "=f"(lo), "=f"(hi) : "l"(v));
}
__device__ __forceinline__ void ffma2(unsigned long long& d,
                                      unsigned long long a, unsigned long long b) {
    asm("fma.rn.f32x2 %0, %1, %2, %0;" : "+l"(d) : "l"(a), "l"(b));
}
__device__ __forceinline__ void fadd2(unsigned long long& d, unsigned long long a) {
    asm("add.rn.f32x2 %0, %0, %1;" : "+l"(d) : "l"(a));
}

// ---- cache-policy helpers ----
__device__ __forceinline__ unsigned long long mk_evict_last() {
    unsigned long long pol;
    asm("createpolicy.fractional.L2::evict_last.b64 %0, 1.0;" : "=l"(pol));
    return pol;
}
__device__ __forceinline__ float4 ldg_keep(const float* p, unsigned long long pol) {
    float4 v;
    asm("ld.global.nc.L2::cache_hint.v4.f32 {%0,%1,%2,%3}, [%4], %5;"
        : "=f"(v.x), "=f"(v.y), "=f"(v.z), "=f"(v.w) : "l"(p), "l"(pol));
    return v;
}
__device__ __forceinline__ float4 ldg_cs(const float* p) {
    float4 v;
    asm("ld.global.cs.v4.f32 {%0,%1,%2,%3}, [%4];"
        : "=f"(v.x), "=f"(v.y), "=f"(v.z), "=f"(v.w) : "l"(p));
    return v;
}
__device__ __forceinline__ int ldg_cs_i(const int* p) {
    int v;
    asm("ld.global.cs.s32 %0, [%1];" : "=r"(v) : "l"(p));
    return v;
}
__device__ __forceinline__ void stg_cs(float* p, float4 v) {
    asm("st.global.cs.v4.f32 [%0], {%1,%2,%3,%4};"
        :: "l"(p), "f"(v.x), "f"(v.y), "f"(v.z), "f"(v.w) : "memory");
}

// ---- mbarrier helpers ----
__device__ __forceinline__ uint32_t smem_u32(const void* p) {
    uint32_t a;
    asm("{ .reg .u64 t; cvta.to.shared.u64 t, %1; cvt.u32.u64 %0, t; }"
        : "=r"(a) : "l"(p));
    return a;
}
__device__ __forceinline__ void mbar_init(uint32_t mbar, uint32_t cnt) {
    asm volatile("mbarrier.init.shared.b64 [%0], %1;" :: "r"(mbar), "r"(cnt) : "memory");
}
__device__ __forceinline__ void mbar_arrive(uint32_t mbar) {
    asm volatile("mbarrier.arrive.shared.b64 _, [%0];" :: "r"(mbar) : "memory");
}
__device__ __forceinline__ void mbar_wait(uint32_t mbar, uint32_t ph) {
    uint32_t done;
    asm volatile("{ .reg .pred p; mbarrier.try_wait.parity.acquire.cta.shared::cta.b64 p, [%1], %2; selp.b32 %0, 1, 0, p; }"
                 : "=r"(done) : "r"(mbar), "r"(ph) : "memory");
    while (!done) {
        asm volatile("{ .reg .pred p; mbarrier.try_wait.parity.acquire.cta.shared::cta.b64 p, [%1], %2, 0x989680; selp.b32 %0, 1, 0, p; }"
                     : "=r"(done) : "r"(mbar), "r"(ph) : "memory");
    }
}

// ============================================================
// Kernel 1: binput = fbonds @ W_i ; msgA = relu(binput)
// ============================================================
__global__ __launch_bounds__(256)
void k_binput(const float* __restrict__ fbonds,
              const float* __restrict__ W_i)
{
    __shared__ float Wsh[BFD * HID];
    int t = threadIdx.x;
    for (int i = t; i < BFD * HID; i += 256) Wsh[i] = W_i[i];
    __syncthreads();

    int c4 = t & 31, w = t >> 5;
    int gw = blockIdx.x * 8 + w;
    const int nwarps = gridDim.x * 8;

    for (int row = gw; row < E_BONDS; row += nwarps) {
        const float* fr = fbonds + (size_t)row * BFD;
        float4 acc = make_float4(0.f, 0.f, 0.f, 0.f);
        #pragma unroll
        for (int k = 0; k < BFD; k++) {
            float f = __ldg(fr + k);
            float4 wv = *(const float4*)&Wsh[k * HID + c4 * 4];
            acc.x += f * wv.x; acc.y += f * wv.y;
            acc.z += f * wv.z; acc.w += f * wv.w;
        }
        size_t o = (size_t)row * HID + c4 * 4;
        *(float4*)&g_binput[o] = acc;
        float4 rr;
        rr.x = fmaxf(acc.x, 0.f); rr.y = fmaxf(acc.y, 0.f);
        rr.z = fmaxf(acc.z, 0.f); rr.w = fmaxf(acc.w, 0.f);
        *(float4*)&g_msgA[o] = rr;
    }
}

// ============================================================
// Kernel 2: WARP-SPECIALIZED message pass (R14 + 4-row producer).
//   warps 0..7  = PRODUCERS: gather 16-row tiles, 4 rows/iter
//                 (60 LDG.128 in flight -> 2x MLP vs R14)
//   warps 8..15 = CONSUMERS: GEMM relu(binput + nei @ W_h)
// smem: Wsh 64KB + 16 slots x 8.25KB = 196KB; 1 CTA/SM.
// ============================================================
#define MS_THR 512
__global__ __launch_bounds__(MS_THR, 1)
void k_msgws(const int* __restrict__ bgraph,
             const float* __restrict__ W_h,
             int flag)  // 0: A->B, 1: B->A
{
    extern __shared__ float smem[];
    float* Wsh  = smem;                 // [128][128]
    float* ring = smem + RING_OFF;      // 16 slots x SLOT_F

    __shared__ unsigned long long mbars[NPAIR * 4];  // [pair][slot][full,empty]

    const float* __restrict__ msg_in  = flag ? g_msgB : g_msgA;
    float*       __restrict__ msg_out = flag ? g_msgA : g_msgB;

    const int t  = threadIdx.x;
    const int ln = t & 31;
    const int w  = t >> 5;              // 0..15
    const bool producer = (w < NPAIR);
    const int pair = producer ? w : (w - NPAIR);
    const unsigned long long pol = mk_evict_last();

    for (int i = t; i < (HID * HID) / 4; i += MS_THR)
        ((float4*)Wsh)[i] = ((const float4*)W_h)[i];
    if (t == 0) {
        for (int i = 0; i < NPAIR * 4; i++)
            mbar_init(smem_u32(&mbars[i]), 1);
    }
    __syncthreads();

    const int ntiles = E_BONDS / 16;             // 12500
    const int npairs = gridDim.x * NPAIR;
    const int pid    = blockIdx.x * NPAIR + pair;

    if (producer) {
        // ---------------- PRODUCER: gather, 4 rows/iter ----------------
        int n = 0;
        for (int tile = pid; tile < ntiles; tile += npairs, n++) {
            const int s  = n & 1;
            const int ph = 1 ^ ((n >> 1) & 1);
            mbar_wait(smem_u32(&mbars[pair * 4 + s * 2 + 1]), ph);  // empty[s]

            float* slot = ring + (pair * 2 + s) * SLOT_F;
            const int base = tile * 16;
            #pragma unroll 1
            for (int r = 0; r < 16; r += 4) {
                size_t gr = (size_t)(base + r);
                int e0 = 0, e1 = 0, e2 = 0, e3 = 0;
                if (ln < MAX_NB) {
                    e0 = ldg_cs_i(bgraph + (gr + 0) * MAX_NB + ln);
                    e1 = ldg_cs_i(bgraph + (gr + 1) * MAX_NB + ln);
                    e2 = ldg_cs_i(bgraph + (gr + 2) * MAX_NB + ln);
                    e3 = ldg_cs_i(bgraph + (gr + 3) * MAX_NB + ln);
                }
                float4 s0 = make_float4(0.f, 0.f, 0.f, 0.f);
                float4 s1 = make_float4(0.f, 0.f, 0.f, 0.f);
                float4 s2 = make_float4(0.f, 0.f, 0.f, 0.f);
                float4 s3 = make_float4(0.f, 0.f, 0.f, 0.f);
                #pragma unroll
                for (int nb = 0; nb < MAX_NB; nb++) {
                    int ea = __shfl_sync(0xffffffffu, e0, nb);
                    int eb = __shfl_sync(0xffffffffu, e1, nb);
                    int ec = __shfl_sync(0xffffffffu, e2, nb);
                    int ed = __shfl_sync(0xffffffffu, e3, nb);
                    float4 va = ldg_keep(msg_in + (size_t)ea * HID + ln * 4, pol);
                    float4 vb = ldg_keep(msg_in + (size_t)eb * HID + ln * 4, pol);
                    float4 vc = ldg_keep(msg_in + (size_t)ec * HID + ln * 4, pol);
                    float4 vd = ldg_keep(msg_in + (size_t)ed * HID + ln * 4, pol);
                    s0.x += va.x; s0.y += va.y; s0.z += va.z; s0.w += va.w;
                    s1.x += vb.x; s1.y += vb.y; s1.z += vb.z; s1.w += vb.w;
                    s2.x += vc.x; s2.y += vc.y; s2.z += vc.z; s2.w += vc.w;
                    s3.x += vd.x; s3.y += vd.y; s3.z += vd.z; s3.w += vd.w;
                }
                *(float4*)&slot[(r + 0) * SLOT_S + ln * 4] = s0;
                *(float4*)&slot[(r + 1) * SLOT_S + ln * 4] = s1;
                *(float4*)&slot[(r + 2) * SLOT_S + ln * 4] = s2;
                *(float4*)&slot[(r + 3) * SLOT_S + ln * 4] = s3;
            }
            __syncwarp();
            if (ln == 0) mbar_arrive(smem_u32(&mbars[pair * 4 + s * 2]));  // full[s]
        }
    } else {
        // ---------------- CONSUMER: GEMM ----------------
        const int rg = ln & 1;
        const int cb = (ln >> 1) * 8;
        int n = 0;
        for (int tile = pid; tile < ntiles; tile += npairs, n++) {
            const int s  = n & 1;
            const int ph = (n >> 1) & 1;
            mbar_wait(smem_u32(&mbars[pair * 4 + s * 2]), ph);  // full[s]

            const float* nei = ring + (pair * 2 + s) * SLOT_F;
            const int base = tile * 16;

            unsigned long long acc[8][4];
            #pragma unroll
            for (int i = 0; i < 8; i++) {
                const float* bp = &g_binput[(size_t)(base + rg + 2 * i) * HID + cb];
                float4 b0 = ldg_cs(&bp[0]);
                float4 b1 = ldg_cs(&bp[4]);
                acc[i][0] = pack2(b0.x, b0.y);
                acc[i][1] = pack2(b0.z, b0.w);
                acc[i][2] = pack2(b1.x, b1.y);
                acc[i][3] = pack2(b1.z, b1.w);
            }

            #pragma unroll 2
            for (int k0 = 0; k0 < HID; k0 += 4) {
                float4 nv[8];
                #pragma unroll
                for (int i = 0; i < 8; i++)
                    nv[i] = *(const float4*)&nei[(rg + 2 * i) * SLOT_S + k0];
                #pragma unroll
                for (int j = 0; j < 4; j++) {
                    const float* wr = &Wsh[(k0 + j) * HID + cb];
                    ulonglong2 w0 = *(const ulonglong2*)&wr[0];
                    ulonglong2 w1 = *(const ulonglong2*)&wr[4];
                    #pragma unroll
                    for (int i = 0; i < 8; i++) {
                        float f = ((const float*)&nv[i])[j];
                        unsigned long long p = pack2(f, f);
                        ffma2(acc[i][0], p, w0.x); ffma2(acc[i][1], p, w0.y);
                        ffma2(acc[i][2], p, w1.x); ffma2(acc[i][3], p, w1.y);
                    }
                }
            }
            __syncwarp();
            if (ln == 0) mbar_arrive(smem_u32(&mbars[pair * 4 + s * 2 + 1]));  // empty[s]

            #pragma unroll
            for (int i = 0; i < 8; i++) {
                float4 o0, o1;
                unpack2(acc[i][0], o0.x, o0.y);
                unpack2(acc[i][1], o0.z, o0.w);
                unpack2(acc[i][2], o1.x, o1.y);
                unpack2(acc[i][3], o1.z, o1.w);
                o0.x = fmaxf(o0.x, 0.f); o0.y = fmaxf(o0.y, 0.f);
                o0.z = fmaxf(o0.z, 0.f); o0.w = fmaxf(o0.w, 0.f);
                o1.x = fmaxf(o1.x, 0.f); o1.y = fmaxf(o1.y, 0.f);
                o1.z = fmaxf(o1.z, 0.f); o1.w = fmaxf(o1.w, 0.f);
                float* op = &msg_out[(size_t)(base + rg + 2 * i) * HID + cb];
                stg_cs(&op[0], o0);
                stg_cs(&op[4], o1);
            }
        }
    }
}

// ============================================================
// warp-local gather (for k_atomh)
// ============================================================
__device__ __forceinline__ void gather4(const float* __restrict__ msg_in,
                                        const int*   __restrict__ graph,
                                        int base, int wg, int ln,
                                        float* __restrict__ buf, int stride,
                                        unsigned long long pol)
{
    #pragma unroll
    for (int i = 0; i < 4; i++) {
        int r = wg * 4 + i;
        int e0 = 0;
        if (ln < MAX_NB)
            e0 = ldg_cs_i(graph + (size_t)(base + r) * MAX_NB + ln);
        float4 s = make_float4(0.f, 0.f, 0.f, 0.f);
        #pragma unroll
        for (int nb = 0; nb < MAX_NB; nb++) {
            int e = __shfl_sync(0xffffffffu, e0, nb);
            float4 v = ldg_keep(msg_in + (size_t)e * HID + ln * 4, pol);
            s.x += v.x; s.y += v.y; s.z += v.z; s.w += v.w;
        }
        *(float4*)&buf[r * stride + ln * 4] = s;
    }
}

// ============================================================
// Kernel 3: atom readout (R5 pipelined SIMT, unchanged)
// ============================================================
__global__ __launch_bounds__(256, 2)
void k_atomh(const float* __restrict__ fatoms,
             const int*   __restrict__ agraph,
             const float* __restrict__ W_o,
             const float* __restrict__ b_o)
{
    extern __shared__ float smem[];
    float* Wsh  = smem;                       // [148][128]
    float* ainD = smem + AINP * HID;          // 2 x [32][AINP]
    __shared__ float bsh[HID];

    const int t   = threadIdx.x;
    const int ln  = t & 31;
    const int wg  = t >> 5;
    const int rg  = ln & 7;
    const int cg  = ln >> 3;
    const int wcb = wg * 16;
    const unsigned long long pol = mk_evict_last();

    for (int i = t; i < (AINP * HID) / 4; i += 256) {
        int k = i >> 5;
        int c = (i & 31) * 4;
        float4 v;
        if (k < 128)      v = *(const float4*)&W_o[(size_t)(AFD + k) * HID + c];
        else if (k < AIN) v = *(const float4*)&W_o[(size_t)(k - 128) * HID + c];
        else              v = make_float4(0.f, 0.f, 0.f, 0.f);
        ((float4*)Wsh)[i] = v;
    }
    if (t < HID) bsh[t] = b_o[t];

    const int ntiles = NATOMS / 32;
    int tile = blockIdx.x;
    int cur  = 0;

    auto fill = [&](int tl, float* buf) {
        const int base = tl * 32;
        gather4(g_msgB, agraph, base, wg, ln, buf, AINP, pol);
        #pragma unroll
        for (int i = 0; i < 4; i++) {
            int r = wg * 4 + i;
            if (ln < AFD)
                buf[r * AINP + 128 + ln] = __ldg(fatoms + (size_t)(base + r) * AFD + ln);
            else if (ln < 20)
                buf[r * AINP + 128 + ln] = 0.f;
        }
    };

    if (tile < ntiles) fill(tile, ainD);

    for (; tile < ntiles; tile += gridDim.x) {
        __syncthreads();

        int nxt = tile + gridDim.x;
        if (nxt < ntiles) fill(nxt, ainD + (cur ^ 1) * 32 * AINP);

        const float* ain = ainD + cur * 32 * AINP;
        const int base = tile * 32;

        unsigned long long acc[4][2];
        #pragma unroll
        for (int i = 0; i < 4; i++) { acc[i][0] = 0ull; acc[i][1] = 0ull; }

        #pragma unroll 2
        for (int k0 = 0; k0 < AINP; k0 += 4) {
            float4 n0 = *(const float4*)&ain[(rg +  0) * AINP + k0];
            float4 n1 = *(const float4*)&ain[(rg +  8) * AINP + k0];
            float4 n2 = *(const float4*)&ain[(rg + 16) * AINP + k0];
            float4 n3 = *(const float4*)&ain[(rg + 24) * AINP + k0];
            #pragma unroll
            for (int j = 0; j < 4; j++) {
                ulonglong2 wv = *(const ulonglong2*)&Wsh[(k0 + j) * HID + wcb + cg * 4];
                float f0 = ((const float*)&n0)[j];
                float f1 = ((const float*)&n1)[j];
                float f2 = ((const float*)&n2)[j];
                float f3 = ((const float*)&n3)[j];
                unsigned long long p;
                p = pack2(f0, f0); ffma2(acc[0][0], p, wv.x); ffma2(acc[0][1], p, wv.y);
                p = pack2(f1, f1); ffma2(acc[1][0], p, wv.x); ffma2(acc[1][1], p, wv.y);
                p = pack2(f2, f2); ffma2(acc[2][0], p, wv.x); ffma2(acc[2][1], p, wv.y);
                p = pack2(f3, f3); ffma2(acc[3][0], p, wv.x); ffma2(acc[3][1], p, wv.y);
            }
        }
        unsigned long long b01 = pack2(bsh[wcb + cg * 4 + 0], bsh[wcb + cg * 4 + 1]);
        unsigned long long b23 = pack2(bsh[wcb + cg * 4 + 2], bsh[wcb + cg * 4 + 3]);
        #pragma unroll
        for (int i = 0; i < 4; i++) {
            fadd2(acc[i][0], b01);
            fadd2(acc[i][1], b23);
            float4 o;
            unpack2(acc[i][0], o.x, o.y);
            unpack2(acc[i][1], o.z, o.w);
            o.x = fmaxf(o.x, 0.f); o.y = fmaxf(o.y, 0.f);
            o.z = fmaxf(o.z, 0.f); o.w = fmaxf(o.w, 0.f);
            *(float4*)&g_atomh[(size_t)(base + rg + 8 * i) * HID + wcb + cg * 4] = o;
        }
        cur ^= 1;
    }
}

// ============================================================
// Kernel 4: segment mean pooling.
// ============================================================
__global__ void k_pool(const int* __restrict__ scope_start,
                       const int* __restrict__ scope_len,
                       float* __restrict__ out)
{
    int m = blockIdx.x, t = threadIdx.x;
    int s = scope_start[m], L = scope_len[m];
    float acc = 0.f;
    for (int i = 0; i < L; i++)
        acc += g_atomh[(size_t)(s + i) * HID + t];
    out[(size_t)m * HID + t] = acc / (float)L;
}

// ============================================================
extern "C" void kernel_launch(void* const* d_in, const int* in_sizes, int n_in,
                              void* d_out, int out_size)
{
    const float* fatoms      = (const float*)d_in[0];
    const float* fbonds      = (const float*)d_in[1];
    const int*   agraph      = (const int*)  d_in[2];
    const int*   bgraph      = (const int*)  d_in[3];
    const int*   scope_start = (const int*)  d_in[4];
    const int*   scope_len   = (const int*)  d_in[5];
    const float* W_i         = (const float*)d_in[6];
    const float* W_h         = (const float*)d_in[7];
    const float* W_o         = (const float*)d_in[8];
    const float* b_o         = (const float*)d_in[9];
    float* out = (float*)d_out;

    const int SMEM3 = (AINP * HID + 2 * 32 * AINP) * 4;   // 113664

    cudaFuncSetAttribute(k_msgws, cudaFuncAttributeMaxDynamicSharedMemorySize, MS_SMEM);
    cudaFuncSetAttribute(k_atomh, cudaFuncAttributeMaxDynamicSharedMemorySize, SMEM3);

    k_binput<<<1024, 256>>>(fbonds, W_i);

    for (int d = 0; d < NPASS; d++)
        k_msgws<<<148, MS_THR, MS_SMEM>>>(bgraph, W_h, d & 1);

    k_atomh<<<296, 256, SMEM3>>>(fatoms, agraph, W_o, b_o);

    k_pool<<<NMOLS, 128>>>(scope_start, scope_len, out);
}

// round 16
// speedup vs baseline: 1.1196x; 1.1196x over previous
#include <cuda_runtime.h>
#include <cstddef>
#include <cstdint>

#define E_BONDS   200000
#define NATOMS    100000
#define HID       128
#define MAX_NB    15
#define BFD       23
#define AFD       18
#define AIN       146
#define AINP      148
#define NMOLS     2000
#define NPASS     5

#define NGRP      4              // groups per CTA: 3 producers + 1 consumer each
#define NPROD     (NGRP * 3)     // 12 producer warps
#define SLOT_S    132            // slot row stride (floats); conflict-free
#define SLOT_F    (16 * SLOT_S)  // floats per slot (16-row tile)
#define RING_OFF  (HID * HID)
#define MS_SMEM   ((HID * HID + NPROD * SLOT_F) * 4)   // 166912 B

// ---- scratch ----
__device__ float g_binput[(size_t)E_BONDS * HID];
__device__ float g_msgA  [(size_t)E_BONDS * HID];
__device__ float g_msgB  [(size_t)E_BONDS * HID];
__device__ float g_atomh [(size_t)NATOMS  * HID];

// ---- packed f32x2 helpers ----
__device__ __forceinline__ unsigned long long pack2(float lo, float hi) {
    unsigned long long r;
    asm("mov.b64 %0, {%1, %2};" : "=l"(r) : "f"(lo), "f"(hi));
    return r;
}
__device__ __forceinline__ void unpack2(unsigned long long v, float& lo, float& hi) {
    asm("mov.b64 {%0, %1}, %2;" : "=f"(lo), "=f"(hi) : "l"(v));
}
__device__ __forceinline__ void ffma2(unsigned long long& d,
                                      unsigned long long a, unsigned long long b) {
    asm("fma.rn.f32x2 %0, %1, %2, %0;" : "+l"(d) : "l"(a), "l"(b));
}
__device__ __forceinline__ void fadd2(unsigned long long& d, unsigned long long a) {
    asm("add.rn.f32x2 %0, %0, %1;" : "+l"(d) : "l"(a));
}

// ---- cache-policy helpers ----
__device__ __forceinline__ unsigned long long mk_evict_last() {
    unsigned long long pol;
    asm("createpolicy.fractional.L2::evict_last.b64 %0, 1.0;" : "=l"(pol));
    return pol;
}
__device__ __forceinline__ float4 ldg_keep(const float* p, unsigned long long pol) {
    float4 v;
    asm("ld.global.nc.L2::cache_hint.v4.f32 {%0,%1,%2,%3}, [%4], %5;"
        : "=f"(v.x), "=f"(v.y), "=f"(v.z), "=f"(v.w) : "l"(p), "l"(pol));
    return v;
}
__device__ __forceinline__ float4 ldg_cs(const float* p) {
    float4 v;
    asm("ld.global.cs.v4.f32 {%0,%1,%2,%3}, [%4];"
        : "=f"(v.x), "=f"(v.y), "=f"(v.z), "=f"(v.w) : "l"(p));
    return v;
}
__device__ __forceinline__ int ldg_cs_i(const int* p) {
    int v;
    asm("ld.global.cs.s32 %0, [%1];" : "=r"(v) : "l"(p));
    return v;
}
__device__ __forceinline__ void stg_cs(float* p, float4 v) {
    asm("st.global.cs.v4.f32 [%0], {%1,%2,%3,%4};"
        :: "l"(p), "f"(v.x), "f"(v.y), "f"(v.z), "f"(v.w) : "memory");
}

// ---- mbarrier helpers ----
__device__ __forceinline__ uint32_t smem_u32(const void* p) {
    uint32_t a;
    asm("{ .reg .u64 t; cvta.to.shared.u64 t, %1; cvt.u32.u64 %0, t; }"
        : "=r"(a) : "l"(p));
    return a;
}
__device__ __forceinline__ void mbar_init(uint32_t mbar, uint32_t cnt) {
    asm volatile("mbarrier.init.shared.b64 [%0], %1;" :: "r"(mbar), "r"(cnt) : "memory");
}
__device__ __forceinline__ void mbar_arrive(uint32_t mbar) {
    asm volatile("mbarrier.arrive.shared.b64 _, [%0];" :: "r"(mbar) : "memory");
}
__device__ __forceinline__ void mbar_wait(uint32_t mbar, uint32_t ph) {
    uint32_t done;
    asm volatile("{ .reg .pred p; mbarrier.try_wait.parity.acquire.cta.shared::cta.b64 p, [%1], %2; selp.b32 %0, 1, 0, p; }"
                 : "=r"(done) : "r"(mbar), "r"(ph) : "memory");
    while (!done) {
        asm volatile("{ .reg .pred p; mbarrier.try_wait.parity.acquire.cta.shared::cta.b64 p, [%1], %2, 0x989680; selp.b32 %0, 1, 0, p; }"
                     : "=r"(done) : "r"(mbar), "r"(ph) : "memory");
    }
}

// ============================================================
// Kernel 1: binput = fbonds @ W_i ; msgA = relu(binput)
// ============================================================
__global__ __launch_bounds__(256)
void k_binput(const float* __restrict__ fbonds,
              const float* __restrict__ W_i)
{
    __shared__ float Wsh[BFD * HID];
    int t = threadIdx.x;
    for (int i = t; i < BFD * HID; i += 256) Wsh[i] = W_i[i];
    __syncthreads();

    int c4 = t & 31, w = t >> 5;
    int gw = blockIdx.x * 8 + w;
    const int nwarps = gridDim.x * 8;

    for (int row = gw; row < E_BONDS; row += nwarps) {
        const float* fr = fbonds + (size_t)row * BFD;
        float4 acc = make_float4(0.f, 0.f, 0.f, 0.f);
        #pragma unroll
        for (int k = 0; k < BFD; k++) {
            float f = __ldg(fr + k);
            float4 wv = *(const float4*)&Wsh[k * HID + c4 * 4];
            acc.x += f * wv.x; acc.y += f * wv.y;
            acc.z += f * wv.z; acc.w += f * wv.w;
        }
        size_t o = (size_t)row * HID + c4 * 4;
        *(float4*)&g_binput[o] = acc;
        float4 rr;
        rr.x = fmaxf(acc.x, 0.f); rr.y = fmaxf(acc.y, 0.f);
        rr.z = fmaxf(acc.z, 0.f); rr.w = fmaxf(acc.w, 0.f);
        *(float4*)&g_msgA[o] = rr;
    }
}

// ============================================================
// Kernel 2: WARP-SPECIALIZED message pass, 12:4 split.
//   4 groups/CTA, group = 3 PRODUCER warps (each with a private
//   single-buffered slot) + 1 CONSUMER warp draining round-robin.
//   Producers are the bottleneck (latency-bound gather) -> 1.5x
//   more of them than R14; consumers (1/SMSP) saturate FFMA2.
// smem: Wsh 64KB + 12 slots x 8.25KB = 163KB; 1 CTA/SM.
// ============================================================
#define MS_THR 512
__global__ __launch_bounds__(MS_THR, 1)
void k_msgws(const int* __restrict__ bgraph,
             const float* __restrict__ W_h,
             int flag)  // 0: A->B, 1: B->A
{
    extern __shared__ float smem[];
    float* Wsh  = smem;                 // [128][128]
    float* ring = smem + RING_OFF;      // 12 slots x SLOT_F

    __shared__ unsigned long long mbars[NPROD * 2];  // [slot][full,empty]

    const float* __restrict__ msg_in  = flag ? g_msgB : g_msgA;
    float*       __restrict__ msg_out = flag ? g_msgA : g_msgB;

    const int t  = threadIdx.x;
    const int ln = t & 31;
    const int w  = t >> 5;              // 0..15
    const bool producer = (w < NPROD);
    const int grp = producer ? (w / 3) : (w - NPROD);   // 0..3
    const int pp  = producer ? (w - grp * 3) : 0;       // producer idx in group
    const unsigned long long pol = mk_evict_last();

    for (int i = t; i < (HID * HID) / 4; i += MS_THR)
        ((float4*)Wsh)[i] = ((const float4*)W_h)[i];
    if (t == 0) {
        for (int i = 0; i < NPROD * 2; i++)
            mbar_init(smem_u32(&mbars[i]), 1);
    }
    __syncthreads();

    const int ntiles  = E_BONDS / 16;            // 12500
    const int ngroups = gridDim.x * NGRP;
    const int gid     = blockIdx.x * NGRP + grp;

    if (producer) {
        // ---------- PRODUCER: gather into private slot ----------
        const int slot_id = grp * 3 + pp;
        float* slot = ring + slot_id * SLOT_F;
        int k = 0;
        for (int n = pp; ; n += 3, k++) {
            const int tile = gid + n * ngroups;
            if (tile >= ntiles) break;
            mbar_wait(smem_u32(&mbars[slot_id * 2 + 1]), 1 ^ (k & 1));  // empty

            const int base = tile * 16;
            #pragma unroll 1
            for (int r = 0; r < 16; r += 2) {
                size_t gr0 = (size_t)(base + r);
                int e0 = (ln < MAX_NB) ? ldg_cs_i(bgraph + gr0 * MAX_NB + ln) : 0;
                int e1 = (ln < MAX_NB) ? ldg_cs_i(bgraph + (gr0 + 1) * MAX_NB + ln) : 0;
                float4 s0 = make_float4(0.f, 0.f, 0.f, 0.f);
                float4 s1 = make_float4(0.f, 0.f, 0.f, 0.f);
                #pragma unroll
                for (int nb = 0; nb < MAX_NB; nb++) {
                    int ea = __shfl_sync(0xffffffffu, e0, nb);
                    int eb = __shfl_sync(0xffffffffu, e1, nb);
                    float4 va = ldg_keep(msg_in + (size_t)ea * HID + ln * 4, pol);
                    float4 vb = ldg_keep(msg_in + (size_t)eb * HID + ln * 4, pol);
                    s0.x += va.x; s0.y += va.y; s0.z += va.z; s0.w += va.w;
                    s1.x += vb.x; s1.y += vb.y; s1.z += vb.z; s1.w += vb.w;
                }
                *(float4*)&slot[(r + 0) * SLOT_S + ln * 4] = s0;
                *(float4*)&slot[(r + 1) * SLOT_S + ln * 4] = s1;
            }
            __syncwarp();
            if (ln == 0) mbar_arrive(smem_u32(&mbars[slot_id * 2]));  // full
        }
    } else {
        // ---------- CONSUMER: GEMM, drain 3 slots round-robin ----------
        const int rg = ln & 1;
        const int cb = (ln >> 1) * 8;
        for (int n = 0; ; n++) {
            const int tile = gid + n * ngroups;
            if (tile >= ntiles) break;
            const int s  = n % 3;
            const int ph = (n / 3) & 1;
            const int slot_id = grp * 3 + s;
            mbar_wait(smem_u32(&mbars[slot_id * 2]), ph);   // full

            const float* nei = ring + slot_id * SLOT_F;
            const int base = tile * 16;

            unsigned long long acc[8][4];
            #pragma unroll
            for (int i = 0; i < 8; i++) {
                const float* bp = &g_binput[(size_t)(base + rg + 2 * i) * HID + cb];
                float4 b0 = ldg_cs(&bp[0]);
                float4 b1 = ldg_cs(&bp[4]);
                acc[i][0] = pack2(b0.x, b0.y);
                acc[i][1] = pack2(b0.z, b0.w);
                acc[i][2] = pack2(b1.x, b1.y);
                acc[i][3] = pack2(b1.z, b1.w);
            }

            #pragma unroll 2
            for (int k0 = 0; k0 < HID; k0 += 4) {
                float4 nv[8];
                #pragma unroll
                for (int i = 0; i < 8; i++)
                    nv[i] = *(const float4*)&nei[(rg + 2 * i) * SLOT_S + k0];
                #pragma unroll
                for (int j = 0; j < 4; j++) {
                    const float* wr = &Wsh[(k0 + j) * HID + cb];
                    ulonglong2 w0 = *(const ulonglong2*)&wr[0];
                    ulonglong2 w1 = *(const ulonglong2*)&wr[4];
                    #pragma unroll
                    for (int i = 0; i < 8; i++) {
                        float f = ((const float*)&nv[i])[j];
                        unsigned long long p = pack2(f, f);
                        ffma2(acc[i][0], p, w0.x); ffma2(acc[i][1], p, w0.y);
                        ffma2(acc[i][2], p, w1.x); ffma2(acc[i][3], p, w1.y);
                    }
                }
            }
            __syncwarp();
            if (ln == 0) mbar_arrive(smem_u32(&mbars[slot_id * 2 + 1]));  // empty

            #pragma unroll
            for (int i = 0; i < 8; i++) {
                float4 o0, o1;
                unpack2(acc[i][0], o0.x, o0.y);
                unpack2(acc[i][1], o0.z, o0.w);
                unpack2(acc[i][2], o1.x, o1.y);
                unpack2(acc[i][3], o1.z, o1.w);
                o0.x = fmaxf(o0.x, 0.f); o0.y = fmaxf(o0.y, 0.f);
                o0.z = fmaxf(o0.z, 0.f); o0.w = fmaxf(o0.w, 0.f);
                o1.x = fmaxf(o1.x, 0.f); o1.y = fmaxf(o1.y, 0.f);
                o1.z = fmaxf(o1.z, 0.f); o1.w = fmaxf(o1.w, 0.f);
                float* op = &msg_out[(size_t)(base + rg + 2 * i) * HID + cb];
                stg_cs(&op[0], o0);
                stg_cs(&op[4], o1);
            }
        }
    }
}

// ============================================================
// warp-local gather (for k_atomh)
// ============================================================
__device__ __forceinline__ void gather4(const float* __restrict__ msg_in,
                                        const int*   __restrict__ graph,
                                        int base, int wg, int ln,
                                        float* __restrict__ buf, int stride,
                                        unsigned long long pol)
{
    #pragma unroll
    for (int i = 0; i < 4; i++) {
        int r = wg * 4 + i;
        int e0 = 0;
        if (ln < MAX_NB)
            e0 = ldg_cs_i(graph + (size_t)(base + r) * MAX_NB + ln);
        float4 s = make_float4(0.f, 0.f, 0.f, 0.f);
        #pragma unroll
        for (int nb = 0; nb < MAX_NB; nb++) {
            int e = __shfl_sync(0xffffffffu, e0, nb);
            float4 v = ldg_keep(msg_in + (size_t)e * HID + ln * 4, pol);
            s.x += v.x; s.y += v.y; s.z += v.z; s.w += v.w;
        }
        *(float4*)&buf[r * stride + ln * 4] = s;
    }
}

// ============================================================
// Kernel 3: atom readout (R5 pipelined SIMT, unchanged)
// ============================================================
__global__ __launch_bounds__(256, 2)
void k_atomh(const float* __restrict__ fatoms,
             const int*   __restrict__ agraph,
             const float* __restrict__ W_o,
             const float* __restrict__ b_o)
{
    extern __shared__ float smem[];
    float* Wsh  = smem;                       // [148][128]
    float* ainD = smem + AINP * HID;          // 2 x [32][AINP]
    __shared__ float bsh[HID];

    const int t   = threadIdx.x;
    const int ln  = t & 31;
    const int wg  = t >> 5;
    const int rg  = ln & 7;
    const int cg  = ln >> 3;
    const int wcb = wg * 16;
    const unsigned long long pol = mk_evict_last();

    for (int i = t; i < (AINP * HID) / 4; i += 256) {
        int k = i >> 5;
        int c = (i & 31) * 4;
        float4 v;
        if (k < 128)      v = *(const float4*)&W_o[(size_t)(AFD + k) * HID + c];
        else if (k < AIN) v = *(const float4*)&W_o[(size_t)(k - 128) * HID + c];
        else              v = make_float4(0.f, 0.f, 0.f, 0.f);
        ((float4*)Wsh)[i] = v;
    }
    if (t < HID) bsh[t] = b_o[t];

    const int ntiles = NATOMS / 32;
    int tile = blockIdx.x;
    int cur  = 0;

    auto fill = [&](int tl, float* buf) {
        const int base = tl * 32;
        gather4(g_msgB, agraph, base, wg, ln, buf, AINP, pol);
        #pragma unroll
        for (int i = 0; i < 4; i++) {
            int r = wg * 4 + i;
            if (ln < AFD)
                buf[r * AINP + 128 + ln] = __ldg(fatoms + (size_t)(base + r) * AFD + ln);
            else if (ln < 20)
                buf[r * AINP + 128 + ln] = 0.f;
        }
    };

    if (tile < ntiles) fill(tile, ainD);

    for (; tile < ntiles; tile += gridDim.x) {
        __syncthreads();

        int nxt = tile + gridDim.x;
        if (nxt < ntiles) fill(nxt, ainD + (cur ^ 1) * 32 * AINP);

        const float* ain = ainD + cur * 32 * AINP;
        const int base = tile * 32;

        unsigned long long acc[4][2];
        #pragma unroll
        for (int i = 0; i < 4; i++) { acc[i][0] = 0ull; acc[i][1] = 0ull; }

        #pragma unroll 2
        for (int k0 = 0; k0 < AINP; k0 += 4) {
            float4 n0 = *(const float4*)&ain[(rg +  0) * AINP + k0];
            float4 n1 = *(const float4*)&ain[(rg +  8) * AINP + k0];
            float4 n2 = *(const float4*)&ain[(rg + 16) * AINP + k0];
            float4 n3 = *(const float4*)&ain[(rg + 24) * AINP + k0];
            #pragma unroll
            for (int j = 0; j < 4; j++) {
                ulonglong2 wv = *(const ulonglong2*)&Wsh[(k0 + j) * HID + wcb + cg * 4];
                float f0 = ((const float*)&n0)[j];
                float f1 = ((const float*)&n1)[j];
                float f2 = ((const float*)&n2)[j];
                float f3 = ((const float*)&n3)[j];
                unsigned long long p;
                p = pack2(f0, f0); ffma2(acc[0][0], p, wv.x); ffma2(acc[0][1], p, wv.y);
                p = pack2(f1, f1); ffma2(acc[1][0], p, wv.x); ffma2(acc[1][1], p, wv.y);
                p = pack2(f2, f2); ffma2(acc[2][0], p, wv.x); ffma2(acc[2][1], p, wv.y);
                p = pack2(f3, f3); ffma2(acc[3][0], p, wv.x); ffma2(acc[3][1], p, wv.y);
            }
        }
        unsigned long long b01 = pack2(bsh[wcb + cg * 4 + 0], bsh[wcb + cg * 4 + 1]);
        unsigned long long b23 = pack2(bsh[wcb + cg * 4 + 2], bsh[wcb + cg * 4 + 3]);
        #pragma unroll
        for (int i = 0; i < 4; i++) {
            fadd2(acc[i][0], b01);
            fadd2(acc[i][1], b23);
            float4 o;
            unpack2(acc[i][0], o.x, o.y);
            unpack2(acc[i][1], o.z, o.w);
            o.x = fmaxf(o.x, 0.f); o.y = fmaxf(o.y, 0.f);
            o.z = fmaxf(o.z, 0.f); o.w = fmaxf(o.w, 0.f);
            *(float4*)&g_atomh[(size_t)(base + rg + 8 * i) * HID + wcb + cg * 4] = o;
        }
        cur ^= 1;
    }
}

// ============================================================
// Kernel 4: segment mean pooling.
// ============================================================
__global__ void k_pool(const int* __restrict__ scope_start,
                       const int* __restrict__ scope_len,
                       float* __restrict__ out)
{
    int m = blockIdx.x, t = threadIdx.x;
    int s = scope_start[m], L = scope_len[m];
    float acc = 0.f;
    for (int i = 0; i < L; i++)
        acc += g_atomh[(size_t)(s + i) * HID + t];
    out[(size_t)m * HID + t] = acc / (float)L;
}

// ============================================================
extern "C" void kernel_launch(void* const* d_in, const int* in_sizes, int n_in,
                              void* d_out, int out_size)
{
    const float* fatoms      = (const float*)d_in[0];
    const float* fbonds      = (const float*)d_in[1];
    const int*   agraph      = (const int*)  d_in[2];
    const int*   bgraph      = (const int*)  d_in[3];
    const int*   scope_start = (const int*)  d_in[4];
    const int*   scope_len   = (const int*)  d_in[5];
    const float* W_i         = (const float*)d_in[6];
    const float* W_h         = (const float*)d_in[7];
    const float* W_o         = (const float*)d_in[8];
    const float* b_o         = (const float*)d_in[9];
    float* out = (float*)d_out;

    const int SMEM3 = (AINP * HID + 2 * 32 * AINP) * 4;   // 113664

    cudaFuncSetAttribute(k_msgws, cudaFuncAttributeMaxDynamicSharedMemorySize, MS_SMEM);
    cudaFuncSetAttribute(k_atomh, cudaFuncAttributeMaxDynamicSharedMemorySize, SMEM3);

    k_binput<<<1024, 256>>>(fbonds, W_i);

    for (int d = 0; d < NPASS; d++)
        k_msgws<<<148, MS_THR, MS_SMEM>>>(bgraph, W_h, d & 1);

    k_atomh<<<296, 256, SMEM3>>>(fatoms, agraph, W_o, b_o);

    k_pool<<<NMOLS, 128>>>(scope_start, scope_len, out);
}

// round 17
// speedup vs baseline: 1.1443x; 1.0221x over previous
#include <cuda_runtime.h>
#include <cstddef>
#include <cstdint>

#define E_BONDS   200000
#define NATOMS    100000
#define HID       128
#define MAX_NB    15
#define BFD       23
#define AFD       18
#define AIN       146
#define AINP      148
#define NMOLS     2000
#define NPASS     5

#define NGRP      4              // groups per CTA: 3 producers + 1 consumer
#define NPROD     (NGRP * 3)     // 12 producer warps
#define SLOT_S    132            // msgws slot row stride (floats)
#define SLOT_F    (16 * SLOT_S)
#define RING_OFF  (HID * HID)
#define MS_SMEM   ((HID * HID + NPROD * SLOT_F) * 4)      // 166912 B

// atomh WS geometry
#define ASLOT_S   AINP                  // 148 floats/row (592B, 16B-aligned)
#define ASLOT_F   (16 * ASLOT_S)
#define ARING_OFF (AINP * HID)
#define AT_SMEM   ((AINP * HID + NPROD * ASLOT_F) * 4)    // 189440 B

// ---- scratch ----
__device__ float g_binput[(size_t)E_BONDS * HID];
__device__ float g_msgA  [(size_t)E_BONDS * HID];
__device__ float g_msgB  [(size_t)E_BONDS * HID];
__device__ float g_atomh [(size_t)NATOMS  * HID];

// ---- packed f32x2 helpers ----
__device__ __forceinline__ unsigned long long pack2(float lo, float hi) {
    unsigned long long r;
    asm("mov.b64 %0, {%1, %2};" : "=l"(r) : "f"(lo), "f"(hi));
    return r;
}
__device__ __forceinline__ void unpack2(unsigned long long v, float& lo, float& hi) {
    asm("mov.b64 {%0, %1}, %2;" : "=f"(lo), "=f"(hi) : "l"(v));
}
__device__ __forceinline__ void ffma2(unsigned long long& d,
                                      unsigned long long a, unsigned long long b) {
    asm("fma.rn.f32x2 %0, %1, %2, %0;" : "+l"(d) : "l"(a), "l"(b));
}
__device__ __forceinline__ void fadd2(unsigned long long& d, unsigned long long a) {
    asm("add.rn.f32x2 %0, %0, %1;" : "+l"(d) : "l"(a));
}

// ---- cache-policy helpers ----
__device__ __forceinline__ unsigned long long mk_evict_last() {
    unsigned long long pol;
    asm("createpolicy.fractional.L2::evict_last.b64 %0, 1.0;" : "=l"(pol));
    return pol;
}
__device__ __forceinline__ float4 ldg_keep(const float* p, unsigned long long pol) {
    float4 v;
    asm("ld.global.nc.L2::cache_hint.v4.f32 {%0,%1,%2,%3}, [%4], %5;"
        : "=f"(v.x), "=f"(v.y), "=f"(v.z), "=f"(v.w) : "l"(p), "l"(pol));
    return v;
}
__device__ __forceinline__ float4 ldg_cs(const float* p) {
    float4 v;
    asm("ld.global.cs.v4.f32 {%0,%1,%2,%3}, [%4];"
        : "=f"(v.x), "=f"(v.y), "=f"(v.z), "=f"(v.w) : "l"(p));
    return v;
}
__device__ __forceinline__ int ldg_cs_i(const int* p) {
    int v;
    asm("ld.global.cs.s32 %0, [%1];" : "=r"(v) : "l"(p));
    return v;
}
__device__ __forceinline__ void stg_cs(float* p, float4 v) {
    asm("st.global.cs.v4.f32 [%0], {%1,%2,%3,%4};"
        :: "l"(p), "f"(v.x), "f"(v.y), "f"(v.z), "f"(v.w) : "memory");
}

// ---- mbarrier helpers ----
__device__ __forceinline__ uint32_t smem_u32(const void* p) {
    uint32_t a;
    asm("{ .reg .u64 t; cvta.to.shared.u64 t, %1; cvt.u32.u64 %0, t; }"
        : "=r"(a) : "l"(p));
    return a;
}
__device__ __forceinline__ void mbar_init(uint32_t mbar, uint32_t cnt) {
    asm volatile("mbarrier.init.shared.b64 [%0], %1;" :: "r"(mbar), "r"(cnt) : "memory");
}
__device__ __forceinline__ void mbar_arrive(uint32_t mbar) {
    asm volatile("mbarrier.arrive.shared.b64 _, [%0];" :: "r"(mbar) : "memory");
}
__device__ __forceinline__ void mbar_wait(uint32_t mbar, uint32_t ph) {
    uint32_t done;
    asm volatile("{ .reg .pred p; mbarrier.try_wait.parity.acquire.cta.shared::cta.b64 p, [%1], %2; selp.b32 %0, 1, 0, p; }"
                 : "=r"(done) : "r"(mbar), "r"(ph) : "memory");
    while (!done) {
        asm volatile("{ .reg .pred p; mbarrier.try_wait.parity.acquire.cta.shared::cta.b64 p, [%1], %2, 0x989680; selp.b32 %0, 1, 0, p; }"
                     : "=r"(done) : "r"(mbar), "r"(ph) : "memory");
    }
}

// ============================================================
// Kernel 1: binput = fbonds @ W_i ; msgA = relu(binput)
// ============================================================
__global__ __launch_bounds__(256)
void k_binput(const float* __restrict__ fbonds,
              const float* __restrict__ W_i)
{
    __shared__ float Wsh[BFD * HID];
    int t = threadIdx.x;
    for (int i = t; i < BFD * HID; i += 256) Wsh[i] = W_i[i];
    __syncthreads();

    int c4 = t & 31, w = t >> 5;
    int gw = blockIdx.x * 8 + w;
    const int nwarps = gridDim.x * 8;

    for (int row = gw; row < E_BONDS; row += nwarps) {
        const float* fr = fbonds + (size_t)row * BFD;
        float4 acc = make_float4(0.f, 0.f, 0.f, 0.f);
        #pragma unroll
        for (int k = 0; k < BFD; k++) {
            float f = __ldg(fr + k);
            float4 wv = *(const float4*)&Wsh[k * HID + c4 * 4];
            acc.x += f * wv.x; acc.y += f * wv.y;
            acc.z += f * wv.z; acc.w += f * wv.w;
        }
        size_t o = (size_t)row * HID + c4 * 4;
        *(float4*)&g_binput[o] = acc;
        float4 rr;
        rr.x = fmaxf(acc.x, 0.f); rr.y = fmaxf(acc.y, 0.f);
        rr.z = fmaxf(acc.z, 0.f); rr.w = fmaxf(acc.w, 0.f);
        *(float4*)&g_msgA[o] = rr;
    }
}

// ============================================================
// Kernel 2: WARP-SPECIALIZED message pass, 12:4 (R16, unchanged)
// ============================================================
#define MS_THR 512
__global__ __launch_bounds__(MS_THR, 1)
void k_msgws(const int* __restrict__ bgraph,
             const float* __restrict__ W_h,
             int flag)  // 0: A->B, 1: B->A
{
    extern __shared__ float smem[];
    float* Wsh  = smem;                 // [128][128]
    float* ring = smem + RING_OFF;      // 12 slots x SLOT_F

    __shared__ unsigned long long mbars[NPROD * 2];

    const float* __restrict__ msg_in  = flag ? g_msgB : g_msgA;
    float*       __restrict__ msg_out = flag ? g_msgA : g_msgB;

    const int t  = threadIdx.x;
    const int ln = t & 31;
    const int w  = t >> 5;
    const bool producer = (w < NPROD);
    const int grp = producer ? (w / 3) : (w - NPROD);
    const int pp  = producer ? (w - grp * 3) : 0;
    const unsigned long long pol = mk_evict_last();

    for (int i = t; i < (HID * HID) / 4; i += MS_THR)
        ((float4*)Wsh)[i] = ((const float4*)W_h)[i];
    if (t == 0) {
        for (int i = 0; i < NPROD * 2; i++)
            mbar_init(smem_u32(&mbars[i]), 1);
    }
    __syncthreads();

    const int ntiles  = E_BONDS / 16;
    const int ngroups = gridDim.x * NGRP;
    const int gid     = blockIdx.x * NGRP + grp;

    if (producer) {
        const int slot_id = grp * 3 + pp;
        float* slot = ring + slot_id * SLOT_F;
        int k = 0;
        for (int n = pp; ; n += 3, k++) {
            const int tile = gid + n * ngroups;
            if (tile >= ntiles) break;
            mbar_wait(smem_u32(&mbars[slot_id * 2 + 1]), 1 ^ (k & 1));

            const int base = tile * 16;
            #pragma unroll 1
            for (int r = 0; r < 16; r += 2) {
                size_t gr0 = (size_t)(base + r);
                int e0 = (ln < MAX_NB) ? ldg_cs_i(bgraph + gr0 * MAX_NB + ln) : 0;
                int e1 = (ln < MAX_NB) ? ldg_cs_i(bgraph + (gr0 + 1) * MAX_NB + ln) : 0;
                float4 s0 = make_float4(0.f, 0.f, 0.f, 0.f);
                float4 s1 = make_float4(0.f, 0.f, 0.f, 0.f);
                #pragma unroll
                for (int nb = 0; nb < MAX_NB; nb++) {
                    int ea = __shfl_sync(0xffffffffu, e0, nb);
                    int eb = __shfl_sync(0xffffffffu, e1, nb);
                    float4 va = ldg_keep(msg_in + (size_t)ea * HID + ln * 4, pol);
                    float4 vb = ldg_keep(msg_in + (size_t)eb * HID + ln * 4, pol);
                    s0.x += va.x; s0.y += va.y; s0.z += va.z; s0.w += va.w;
                    s1.x += vb.x; s1.y += vb.y; s1.z += vb.z; s1.w += vb.w;
                }
                *(float4*)&slot[(r + 0) * SLOT_S + ln * 4] = s0;
                *(float4*)&slot[(r + 1) * SLOT_S + ln * 4] = s1;
            }
            __syncwarp();
            if (ln == 0) mbar_arrive(smem_u32(&mbars[slot_id * 2]));
        }
    } else {
        const int rg = ln & 1;
        const int cb = (ln >> 1) * 8;
        for (int n = 0; ; n++) {
            const int tile = gid + n * ngroups;
            if (tile >= ntiles) break;
            const int s  = n % 3;
            const int ph = (n / 3) & 1;
            const int slot_id = grp * 3 + s;
            mbar_wait(smem_u32(&mbars[slot_id * 2]), ph);

            const float* nei = ring + slot_id * SLOT_F;
            const int base = tile * 16;

            unsigned long long acc[8][4];
            #pragma unroll
            for (int i = 0; i < 8; i++) {
                const float* bp = &g_binput[(size_t)(base + rg + 2 * i) * HID + cb];
                float4 b0 = ldg_cs(&bp[0]);
                float4 b1 = ldg_cs(&bp[4]);
                acc[i][0] = pack2(b0.x, b0.y);
                acc[i][1] = pack2(b0.z, b0.w);
                acc[i][2] = pack2(b1.x, b1.y);
                acc[i][3] = pack2(b1.z, b1.w);
            }

            #pragma unroll 2
            for (int k0 = 0; k0 < HID; k0 += 4) {
                float4 nv[8];
                #pragma unroll
                for (int i = 0; i < 8; i++)
                    nv[i] = *(const float4*)&nei[(rg + 2 * i) * SLOT_S + k0];
                #pragma unroll
                for (int j = 0; j < 4; j++) {
                    const float* wr = &Wsh[(k0 + j) * HID + cb];
                    ulonglong2 w0 = *(const ulonglong2*)&wr[0];
                    ulonglong2 w1 = *(const ulonglong2*)&wr[4];
                    #pragma unroll
                    for (int i = 0; i < 8; i++) {
                        float f = ((const float*)&nv[i])[j];
                        unsigned long long p = pack2(f, f);
                        ffma2(acc[i][0], p, w0.x); ffma2(acc[i][1], p, w0.y);
                        ffma2(acc[i][2], p, w1.x); ffma2(acc[i][3], p, w1.y);
                    }
                }
            }
            __syncwarp();
            if (ln == 0) mbar_arrive(smem_u32(&mbars[slot_id * 2 + 1]));

            #pragma unroll
            for (int i = 0; i < 8; i++) {
                float4 o0, o1;
                unpack2(acc[i][0], o0.x, o0.y);
                unpack2(acc[i][1], o0.z, o0.w);
                unpack2(acc[i][2], o1.x, o1.y);
                unpack2(acc[i][3], o1.z, o1.w);
                o0.x = fmaxf(o0.x, 0.f); o0.y = fmaxf(o0.y, 0.f);
                o0.z = fmaxf(o0.z, 0.f); o0.w = fmaxf(o0.w, 0.f);
                o1.x = fmaxf(o1.x, 0.f); o1.y = fmaxf(o1.y, 0.f);
                o1.z = fmaxf(o1.z, 0.f); o1.w = fmaxf(o1.w, 0.f);
                float* op = &msg_out[(size_t)(base + rg + 2 * i) * HID + cb];
                stg_cs(&op[0], o0);
                stg_cs(&op[4], o1);
            }
        }
    }
}

// ============================================================
// Kernel 3: WARP-SPECIALIZED atom readout, same 12:4 template.
//   producers: slot cols 0..127 = gather(g_msgB via agraph),
//              cols 128..145 = fatoms, 146..147 = 0
//   consumers: GEMM K=148 vs permuted W_o + bias + relu
// smem: Wsh[148][128] 74KB + 12 slots x 9.25KB = 185KB
// ============================================================
__global__ __launch_bounds__(MS_THR, 1)
void k_atomws(const float* __restrict__ fatoms,
              const int*   __restrict__ agraph,
              const float* __restrict__ W_o,
              const float* __restrict__ b_o)
{
    extern __shared__ float smem[];
    float* Wsh  = smem;                 // [148][128] permuted
    float* ring = smem + ARING_OFF;     // 12 slots x ASLOT_F

    __shared__ unsigned long long mbars[NPROD * 2];
    __shared__ float bsh[HID];

    const int t  = threadIdx.x;
    const int ln = t & 31;
    const int w  = t >> 5;
    const bool producer = (w < NPROD);
    const int grp = producer ? (w / 3) : (w - NPROD);
    const int pp  = producer ? (w - grp * 3) : 0;
    const unsigned long long pol = mk_evict_last();

    // permuted W_o: row k<128 -> W_o[18+k]; 128..145 -> W_o[k-128]; 146,147 -> 0
    for (int i = t; i < (AINP * HID) / 4; i += MS_THR) {
        int k = i >> 5;
        int c = (i & 31) * 4;
        float4 v;
        if (k < 128)      v = *(const float4*)&W_o[(size_t)(AFD + k) * HID + c];
        else if (k < AIN) v = *(const float4*)&W_o[(size_t)(k - 128) * HID + c];
        else              v = make_float4(0.f, 0.f, 0.f, 0.f);
        ((float4*)Wsh)[i] = v;
    }
    if (t < HID) bsh[t] = b_o[t];
    if (t == 0) {
        for (int i = 0; i < NPROD * 2; i++)
            mbar_init(smem_u32(&mbars[i]), 1);
    }
    __syncthreads();

    const int ntiles  = NATOMS / 16;            // 6250
    const int ngroups = gridDim.x * NGRP;
    const int gid     = blockIdx.x * NGRP + grp;

    if (producer) {
        const int slot_id = grp * 3 + pp;
        float* slot = ring + slot_id * ASLOT_F;
        int k = 0;
        for (int n = pp; ; n += 3, k++) {
            const int tile = gid + n * ngroups;
            if (tile >= ntiles) break;
            mbar_wait(smem_u32(&mbars[slot_id * 2 + 1]), 1 ^ (k & 1));

            const int base = tile * 16;
            #pragma unroll 1
            for (int r = 0; r < 16; r += 2) {
                size_t gr0 = (size_t)(base + r);
                int e0 = (ln < MAX_NB) ? ldg_cs_i(agraph + gr0 * MAX_NB + ln) : 0;
                int e1 = (ln < MAX_NB) ? ldg_cs_i(agraph + (gr0 + 1) * MAX_NB + ln) : 0;
                float4 s0 = make_float4(0.f, 0.f, 0.f, 0.f);
                float4 s1 = make_float4(0.f, 0.f, 0.f, 0.f);
                #pragma unroll
                for (int nb = 0; nb < MAX_NB; nb++) {
                    int ea = __shfl_sync(0xffffffffu, e0, nb);
                    int eb = __shfl_sync(0xffffffffu, e1, nb);
                    float4 va = ldg_keep(g_msgB + (size_t)ea * HID + ln * 4, pol);
                    float4 vb = ldg_keep(g_msgB + (size_t)eb * HID + ln * 4, pol);
                    s0.x += va.x; s0.y += va.y; s0.z += va.z; s0.w += va.w;
                    s1.x += vb.x; s1.y += vb.y; s1.z += vb.z; s1.w += vb.w;
                }
                *(float4*)&slot[(r + 0) * ASLOT_S + ln * 4] = s0;
                *(float4*)&slot[(r + 1) * ASLOT_S + ln * 4] = s1;
                // fatoms cols 128..145, zero 146..147
                if (ln < AFD) {
                    slot[(r + 0) * ASLOT_S + 128 + ln] = __ldg(fatoms + gr0 * AFD + ln);
                    slot[(r + 1) * ASLOT_S + 128 + ln] = __ldg(fatoms + (gr0 + 1) * AFD + ln);
                } else if (ln < 20) {
                    slot[(r + 0) * ASLOT_S + 128 + ln] = 0.f;
                    slot[(r + 1) * ASLOT_S + 128 + ln] = 0.f;
                }
            }
            __syncwarp();
            if (ln == 0) mbar_arrive(smem_u32(&mbars[slot_id * 2]));
        }
    } else {
        const int rg = ln & 1;
        const int cb = (ln >> 1) * 8;
        unsigned long long b01, b23, b45, b67;
        b01 = pack2(bsh[cb + 0], bsh[cb + 1]);
        b23 = pack2(bsh[cb + 2], bsh[cb + 3]);
        b45 = pack2(bsh[cb + 4], bsh[cb + 5]);
        b67 = pack2(bsh[cb + 6], bsh[cb + 7]);
        for (int n = 0; ; n++) {
            const int tile = gid + n * ngroups;
            if (tile >= ntiles) break;
            const int s  = n % 3;
            const int ph = (n / 3) & 1;
            const int slot_id = grp * 3 + s;
            mbar_wait(smem_u32(&mbars[slot_id * 2]), ph);

            const float* ain = ring + slot_id * ASLOT_F;
            const int base = tile * 16;

            unsigned long long acc[8][4];
            #pragma unroll
            for (int i = 0; i < 8; i++) {
                acc[i][0] = b01; acc[i][1] = b23;
                acc[i][2] = b45; acc[i][3] = b67;
            }

            #pragma unroll 2
            for (int k0 = 0; k0 < AINP; k0 += 4) {
                float4 nv[8];
                #pragma unroll
                for (int i = 0; i < 8; i++)
                    nv[i] = *(const float4*)&ain[(rg + 2 * i) * ASLOT_S + k0];
                #pragma unroll
                for (int j = 0; j < 4; j++) {
                    const float* wr = &Wsh[(k0 + j) * HID + cb];
                    ulonglong2 w0 = *(const ulonglong2*)&wr[0];
                    ulonglong2 w1 = *(const ulonglong2*)&wr[4];
                    #pragma unroll
                    for (int i = 0; i < 8; i++) {
                        float f = ((const float*)&nv[i])[j];
                        unsigned long long p = pack2(f, f);
                        ffma2(acc[i][0], p, w0.x); ffma2(acc[i][1], p, w0.y);
                        ffma2(acc[i][2], p, w1.x); ffma2(acc[i][3], p, w1.y);
                    }
                }
            }
            __syncwarp();
            if (ln == 0) mbar_arrive(smem_u32(&mbars[slot_id * 2 + 1]));

            #pragma unroll
            for (int i = 0; i < 8; i++) {
                float4 o0, o1;
                unpack2(acc[i][0], o0.x, o0.y);
                unpack2(acc[i][1], o0.z, o0.w);
                unpack2(acc[i][2], o1.x, o1.y);
                unpack2(acc[i][3], o1.z, o1.w);
                o0.x = fmaxf(o0.x, 0.f); o0.y = fmaxf(o0.y, 0.f);
                o0.z = fmaxf(o0.z, 0.f); o0.w = fmaxf(o0.w, 0.f);
                o1.x = fmaxf(o1.x, 0.f); o1.y = fmaxf(o1.y, 0.f);
                o1.z = fmaxf(o1.z, 0.f); o1.w = fmaxf(o1.w, 0.f);
                float* op = &g_atomh[(size_t)(base + rg + 2 * i) * HID + cb];
                *(float4*)&op[0] = o0;
                *(float4*)&op[4] = o1;
            }
        }
    }
}

// ============================================================
// Kernel 4: segment mean pooling.
// ============================================================
__global__ void k_pool(const int* __restrict__ scope_start,
                       const int* __restrict__ scope_len,
                       float* __restrict__ out)
{
    int m = blockIdx.x, t = threadIdx.x;
    int s = scope_start[m], L = scope_len[m];
    float acc = 0.f;
    for (int i = 0; i < L; i++)
        acc += g_atomh[(size_t)(s + i) * HID + t];
    out[(size_t)m * HID + t] = acc / (float)L;
}

// ============================================================
extern "C" void kernel_launch(void* const* d_in, const int* in_sizes, int n_in,
                              void* d_out, int out_size)
{
    const float* fatoms      = (const float*)d_in[0];
    const float* fbonds      = (const float*)d_in[1];
    const int*   agraph      = (const int*)  d_in[2];
    const int*   bgraph      = (const int*)  d_in[3];
    const int*   scope_start = (const int*)  d_in[4];
    const int*   scope_len   = (const int*)  d_in[5];
    const float* W_i         = (const float*)d_in[6];
    const float* W_h         = (const float*)d_in[7];
    const float* W_o         = (const float*)d_in[8];
    const float* b_o         = (const float*)d_in[9];
    float* out = (float*)d_out;

    cudaFuncSetAttribute(k_msgws,  cudaFuncAttributeMaxDynamicSharedMemorySize, MS_SMEM);
    cudaFuncSetAttribute(k_atomws, cudaFuncAttributeMaxDynamicSharedMemorySize, AT_SMEM);

    k_binput<<<1024, 256>>>(fbonds, W_i);

    for (int d = 0; d < NPASS; d++)
        k_msgws<<<148, MS_THR, MS_SMEM>>>(bgraph, W_h, d & 1);

    k_atomws<<<148, MS_THR, AT_SMEM>>>(fatoms, agraph, W_o, b_o);

    k_pool<<<NMOLS, 128>>>(scope_start, scope_len, out);
}